// round 10
// baseline (speedup 1.0000x reference)
#include <cuda_runtime.h>
#include <cuda_fp16.h>
#include <cuda_bf16.h>
#include <math.h>
#include <stdint.h>

#define FIN 128
#define HID 64
#define N_MAX 100032
#define LRELU_ALPHA 0.2f

// ---- scratch (static device globals; no allocation allowed) ----
__device__ __half2 g_fts_h[(size_t)N_MAX * 32];  // seq@W as fp16 [N,64] 12.8MB (L2-resident)
__device__ float   g_f1[N_MAX];
__device__ float   g_f2[N_MAX];
__device__ int     g_rowptr[N_MAX + 1];

// ============================================================================
// K1: seq_fts = seq @ W via warp-level mma.sync bf16 (hi/lo split, fp32 acc).
//   D = Xhi*Whi + Xhi*Wlo + Xlo*Whi  (lo*lo dropped, ~2^-16 rel).
//   CTA: 128 nodes, 256 threads (8 warps), warp = 16 nodes x 64 hid.
//   Smem (dynamic, ~104KB): Xhi/Xlo [128][136] bf16 (pad -> conflict-free),
//   Wphi/Wplo packed k-pairs [64][72] u32 (bf16x2), conflict-free.
//   Epilogue from registers: f1/f2 dots (+2 shfl) and fp16 fts store.
// ============================================================================
#define XS_BYTES   272            // 136 bf16 per node row
#define XHI_OFF    0
#define XLO_OFF    (128 * XS_BYTES)               // 34816
#define WP_STRIDE  72                              // u32 words per k-pair row
#define WPHI_OFF   (XLO_OFF + 128 * XS_BYTES)     // 69632
#define WPLO_OFF   (WPHI_OFF + 64 * WP_STRIDE * 4)// 88064
#define GEMM_SMEM  (WPLO_OFF + 64 * WP_STRIDE * 4)// 106496

__device__ __forceinline__ void bsplit(float x, __nv_bfloat16& hi, __nv_bfloat16& lo) {
    hi = __float2bfloat16(x);
    lo = __float2bfloat16(x - __bfloat162float(hi));
}
__device__ __forceinline__ uint32_t pack_bf2(__nv_bfloat16 a, __nv_bfloat16 b) {
    __nv_bfloat162 t = __halves2bfloat162(a, b);   // a = low (first k)
    return *(uint32_t*)&t;
}

__device__ __forceinline__ void mma16816(float* c, uint32_t a0, uint32_t a1,
                                         uint32_t a2, uint32_t a3,
                                         uint32_t b0, uint32_t b1) {
    asm volatile(
        "mma.sync.aligned.m16n8k16.row.col.f32.bf16.bf16.f32 "
        "{%0,%1,%2,%3}, {%4,%5,%6,%7}, {%8,%9}, {%0,%1,%2,%3};"
        : "+f"(c[0]), "+f"(c[1]), "+f"(c[2]), "+f"(c[3])
        : "r"(a0), "r"(a1), "r"(a2), "r"(a3), "r"(b0), "r"(b1));
}

__global__ void __launch_bounds__(256)
gemm_mma_kernel(const float* __restrict__ seq, const float* __restrict__ W,
                const float* __restrict__ a1, const float* __restrict__ b1,
                const float* __restrict__ a2, const float* __restrict__ b2,
                int N) {
    extern __shared__ char smc[];
    const int tid  = threadIdx.x;
    const int warp = tid >> 5;
    const int lane = tid & 31;
    const int n0   = blockIdx.x * 128;

    // ---- stage X (hi/lo bf16), padded rows ----
    for (int i = tid; i < 128 * 32; i += 256) {
        int node = i >> 5, q = i & 31;
        float4 v = make_float4(0.f, 0.f, 0.f, 0.f);
        if (n0 + node < N)
            v = ((const float4*)(seq + (size_t)(n0 + node) * FIN))[q];
        int k = q * 4;
        __nv_bfloat16 h0, l0, h1, l1, h2, l2, h3, l3;
        bsplit(v.x, h0, l0); bsplit(v.y, h1, l1);
        bsplit(v.z, h2, l2); bsplit(v.w, h3, l3);
        char* phi = smc + XHI_OFF + node * XS_BYTES + k * 2;
        char* plo = smc + XLO_OFF + node * XS_BYTES + k * 2;
        *(uint32_t*)(phi)     = pack_bf2(h0, h1);
        *(uint32_t*)(phi + 4) = pack_bf2(h2, h3);
        *(uint32_t*)(plo)     = pack_bf2(l0, l1);
        *(uint32_t*)(plo + 4) = pack_bf2(l2, l3);
    }
    // ---- stage W as k-pair fragments: Wp[k2][n] = (W[2k2][n], W[2k2+1][n]) ----
    for (int i = tid; i < 64 * 64; i += 256) {
        int k2 = i >> 6, n = i & 63;
        float w0 = W[(2 * k2) * HID + n];
        float w1 = W[(2 * k2 + 1) * HID + n];
        __nv_bfloat16 h0, l0, h1, l1;
        bsplit(w0, h0, l0); bsplit(w1, h1, l1);
        ((uint32_t*)(smc + WPHI_OFF))[k2 * WP_STRIDE + n] = pack_bf2(h0, h1);
        ((uint32_t*)(smc + WPLO_OFF))[k2 * WP_STRIDE + n] = pack_bf2(l0, l1);
    }
    __syncthreads();

    const int g   = lane >> 2;    // group 0..7
    const int tig = lane & 3;     // thread-in-group

    float acc[8][4];
    #pragma unroll
    for (int nf = 0; nf < 8; nf++)
        #pragma unroll
        for (int j = 0; j < 4; j++) acc[nf][j] = 0.f;

    const int rowA = warp * 16 + g;      // local node row (lane's first row)
    const char* xh = smc + XHI_OFF + rowA * XS_BYTES + tig * 4;   // k = tig*2
    const char* xl = smc + XLO_OFF + rowA * XS_BYTES + tig * 4;
    const uint32_t* wh = (const uint32_t*)(smc + WPHI_OFF) + tig * WP_STRIDE + g;
    const uint32_t* wl = (const uint32_t*)(smc + WPLO_OFF) + tig * WP_STRIDE + g;

    #pragma unroll
    for (int p = 0; p < 3; p++) {
        const char* xb = (p < 2) ? xh : xl;
        const uint32_t* wb = (p == 1) ? wl : wh;
        #pragma unroll
        for (int kc = 0; kc < 8; kc++) {
            // A fragment (rows rowA, rowA+8; k-chunk kc)
            const char* xa = xb + kc * 32;                 // +16 k = 32B
            uint32_t A0 = *(const uint32_t*)(xa);
            uint32_t A1 = *(const uint32_t*)(xa + 8 * XS_BYTES);
            uint32_t A2 = *(const uint32_t*)(xa + 16);     // k+8
            uint32_t A3 = *(const uint32_t*)(xa + 8 * XS_BYTES + 16);
            const uint32_t* wkc = wb + kc * 8 * WP_STRIDE;
            #pragma unroll
            for (int nf = 0; nf < 8; nf++) {
                uint32_t B0 = wkc[nf * 8];                     // k' = kc*8+tig
                uint32_t B1 = wkc[4 * WP_STRIDE + nf * 8];     // k' + 4
                mma16816(acc[nf], A0, A1, A2, A3, B0, B1);
            }
        }
    }

    // ---- epilogue: lane owns cols {nf*8+tig*2, +1} of rows rowA and rowA+8 ----
    float p1a = 0.f, p2a = 0.f, p1b = 0.f, p2b = 0.f;
    #pragma unroll
    for (int nf = 0; nf < 8; nf++) {
        int col = nf * 8 + tig * 2;
        float w1a = a1[col], w1b = a1[col + 1];
        float w2a = a2[col], w2b = a2[col + 1];
        p1a += acc[nf][0] * w1a + acc[nf][1] * w1b;
        p2a += acc[nf][0] * w2a + acc[nf][1] * w2b;
        p1b += acc[nf][2] * w1a + acc[nf][3] * w1b;
        p2b += acc[nf][2] * w2a + acc[nf][3] * w2b;
    }
    // reduce across the 4 lanes of the group (lanes g*4 .. g*4+3)
    #pragma unroll
    for (int o = 1; o <= 2; o <<= 1) {
        p1a += __shfl_xor_sync(0xFFFFFFFFu, p1a, o);
        p2a += __shfl_xor_sync(0xFFFFFFFFu, p2a, o);
        p1b += __shfl_xor_sync(0xFFFFFFFFu, p1b, o);
        p2b += __shfl_xor_sync(0xFFFFFFFFu, p2b, o);
    }
    int nA = n0 + rowA;
    int nB = nA + 8;
    if (tig == 0) {
        float bb1 = b1[0], bb2 = b2[0];
        if (nA < N) { g_f1[nA] = p1a + bb1; g_f2[nA] = p2a + bb2; }
        if (nB < N) { g_f1[nB] = p1b + bb1; g_f2[nB] = p2b + bb2; }
    }
    // fts fp16 store: half2 index = nf*4 + tig
    if (nA < N) {
        __half2* dst = g_fts_h + (size_t)nA * 32 + tig;
        #pragma unroll
        for (int nf = 0; nf < 8; nf++)
            dst[nf * 4] = __floats2half2_rn(acc[nf][0], acc[nf][1]);
    }
    if (nB < N) {
        __half2* dst = g_fts_h + (size_t)nB * 32 + tig;
        #pragma unroll
        for (int nf = 0; nf < 8; nf++)
            dst[nf * 4] = __floats2half2_rn(acc[nf][2], acc[nf][3]);
    }
}

// ============================================================================
// K2: CSR row_ptr from sorted edge_row
// ============================================================================
__global__ void build_rowptr(const int* __restrict__ erow, int E, int N) {
    int e = blockIdx.x * blockDim.x + threadIdx.x;
    if (e >= E) return;
    int r = erow[e];
    int rp = (e == 0) ? -1 : erow[e - 1];
    for (int rr = rp + 1; rr <= r; ++rr) g_rowptr[rr] = e;
    if (e == E - 1)
        for (int rr = r + 1; rr <= N; ++rr) g_rowptr[rr] = E;
}

// ============================================================================
// K3: fused logits + segmented softmax + SpMM + ELU. One warp per row (R5).
// ============================================================================
__global__ void __launch_bounds__(256)
attn_kernel(const int* __restrict__ ec, const float* __restrict__ ev,
            float* __restrict__ out, int N) {
    int row  = (blockIdx.x * 256 + threadIdx.x) >> 5;
    int lane = threadIdx.x & 31;
    if (row >= N) return;

    int s = g_rowptr[row];
    int e = g_rowptr[row + 1];
    float f1r = g_f1[row];

    const int half = lane >> 4;
    const int li   = lane & 15;

    float4 accA = make_float4(0.f, 0.f, 0.f, 0.f);
    float4 accB = make_float4(0.f, 0.f, 0.f, 0.f);
    float ssum = 0.f;

    for (int base = s; base < e; base += 32) {
        int idx = base + lane;
        float z = 0.f;
        int c = 0;
        if (idx < e) {
            c = ec[idx];
            float l = ev[idx] * (f1r + g_f2[c]);
            l = fmaxf(l, LRELU_ALPHA * l);
            z = __expf(l);
        }
        ssum += z;
        int cnt = min(32, e - base);

        int j = 0;
        for (; j + 2 < cnt; j += 4) {
            int sA = j + half;
            int sB = j + 2 + half;
            int   cA = __shfl_sync(0xFFFFFFFFu, c, sA);
            float zA = __shfl_sync(0xFFFFFFFFu, z, sA);
            int   cB = __shfl_sync(0xFFFFFFFFu, c, sB);
            float zB = __shfl_sync(0xFFFFFFFFu, z, sB);
            uint2 rA = *(const uint2*)(g_fts_h + (size_t)cA * 32 + li * 2);
            uint2 rB = *(const uint2*)(g_fts_h + (size_t)cB * 32 + li * 2);
            float2 vA0 = __half22float2(*(__half2*)&rA.x);
            float2 vA1 = __half22float2(*(__half2*)&rA.y);
            float2 vB0 = __half22float2(*(__half2*)&rB.x);
            float2 vB1 = __half22float2(*(__half2*)&rB.y);
            accA.x += zA * vA0.x; accA.y += zA * vA0.y;
            accA.z += zA * vA1.x; accA.w += zA * vA1.y;
            accB.x += zB * vB0.x; accB.y += zB * vB0.y;
            accB.z += zB * vB1.x; accB.w += zB * vB1.y;
        }
        if (j < cnt) {
            int sA = j + half;
            int   cA = __shfl_sync(0xFFFFFFFFu, c, sA);
            float zA = __shfl_sync(0xFFFFFFFFu, z, sA);
            uint2 rA = *(const uint2*)(g_fts_h + (size_t)cA * 32 + li * 2);
            float2 vA0 = __half22float2(*(__half2*)&rA.x);
            float2 vA1 = __half22float2(*(__half2*)&rA.y);
            accA.x += zA * vA0.x; accA.y += zA * vA0.y;
            accA.z += zA * vA1.x; accA.w += zA * vA1.y;
        }
    }

    float4 acc = make_float4(accA.x + accB.x, accA.y + accB.y,
                             accA.z + accB.z, accA.w + accB.w);
    acc.x += __shfl_xor_sync(0xFFFFFFFFu, acc.x, 16);
    acc.y += __shfl_xor_sync(0xFFFFFFFFu, acc.y, 16);
    acc.z += __shfl_xor_sync(0xFFFFFFFFu, acc.z, 16);
    acc.w += __shfl_xor_sync(0xFFFFFFFFu, acc.w, 16);
    #pragma unroll
    for (int o = 16; o; o >>= 1) ssum += __shfl_xor_sync(0xFFFFFFFFu, ssum, o);

    if (half == 0) {
        float4 o4 = make_float4(0.f, 0.f, 0.f, 0.f);
        if (e > s) {
            float inv = 1.f / ssum;
            o4 = make_float4(acc.x * inv, acc.y * inv, acc.z * inv, acc.w * inv);
        }
        o4.x = o4.x > 0.f ? o4.x : expm1f(o4.x);
        o4.y = o4.y > 0.f ? o4.y : expm1f(o4.y);
        o4.z = o4.z > 0.f ? o4.z : expm1f(o4.z);
        o4.w = o4.w > 0.f ? o4.w : expm1f(o4.w);
        *(float4*)(out + (size_t)row * HID + li * 4) = o4;
    }
}

// ============================================================================
// launch
// ============================================================================
extern "C" void kernel_launch(void* const* d_in, const int* in_sizes, int n_in,
                              void* d_out, int out_size) {
    const float* seq = (const float*)d_in[0];
    const int*   er  = (const int*)d_in[1];
    const int*   ec  = (const int*)d_in[2];
    const float* ev  = (const float*)d_in[3];
    const float* W   = (const float*)d_in[4];
    const float* a1  = (const float*)d_in[5];
    const float* b1  = (const float*)d_in[6];
    const float* a2  = (const float*)d_in[7];
    const float* b2  = (const float*)d_in[8];
    // d_in[9] = bias_zero (all zeros — no-op)
    float* out = (float*)d_out;

    int N = in_sizes[0] / FIN;   // seq is [1, N, 128]
    int E = in_sizes[1];

    cudaFuncSetAttribute(gemm_mma_kernel,
                         cudaFuncAttributeMaxDynamicSharedMemorySize, GEMM_SMEM);

    gemm_mma_kernel<<<(N + 127) / 128, 256, GEMM_SMEM>>>(seq, W, a1, b1, a2, b2, N);
    build_rowptr<<<(E + 255) / 256, 256>>>(er, E, N);
    attn_kernel<<<(N + 7) / 8, 256>>>(ec, ev, out, N);
}